// round 4
// baseline (speedup 1.0000x reference)
#include <cuda_runtime.h>
#include <cstdint>

// Problem constants
#define BB   512
#define SS   1024
#define INW  32
#define HH   128
#define GG   512          // 4*H
#define KK   160          // H + IN
#define RR   4            // batch rows per CTA
#define NBLK 128          // 512 / RR
#define NTHR 256          // each thread: 2 gates x 4 rows
#define WREG 72           // weight floats per gate in registers (k = 0..71), 18 quads
#define WSM  88           // per gate in smem: Whh[72:128)=56 + Wih 32, 22 quads
#define WSTRIDE 92        // 88 + 4 pad; gcd(92 mod 32 = 28, 32) = 4 -> 4-phase conflict-free LDS.128

#define W_SH_FLOATS (GG * WSTRIDE)                       // 47104
#define HX_FLOATS   (RR * KK)                            // 640: per row 0..127 = h, 128..159 = x
#define G_SH_FLOATS (RR * GG)                            // 2048
#define SMEM_FLOATS (W_SH_FLOATS + HX_FLOATS + G_SH_FLOATS)
#define SMEM_BYTES  (SMEM_FLOATS * 4)                    // 199168 B < 227 KiB cap

// Packed fp32x2 FMA (Blackwell; ptxas never emits it from C++)
__device__ __forceinline__ unsigned long long ffma2(unsigned long long a,
                                                    unsigned long long b,
                                                    unsigned long long c) {
    unsigned long long d;
    asm("fma.rn.f32x2 %0, %1, %2, %3;" : "=l"(d) : "l"(a), "l"(b), "l"(c));
    return d;
}

__device__ __forceinline__ void unpack2(unsigned long long v, float& lo, float& hi) {
    asm("mov.b64 {%0, %1}, %2;" : "=f"(lo), "=f"(hi) : "l"(v));
}

__device__ __forceinline__ float sigmoid_f(float v) {
    return __fdividef(1.0f, 1.0f + __expf(-v));
}
__device__ __forceinline__ float tanh_f(float v) {
    return 1.0f - __fdividef(2.0f, __expf(2.0f * v) + 1.0f);
}

__global__ void __launch_bounds__(NTHR, 1)
lstm_fused_kernel(const float* __restrict__ x,     // [B,S,IN]
                  const float* __restrict__ Wih,   // [4H,IN]
                  const float* __restrict__ Whh,   // [4H,H]
                  const float* __restrict__ bih,   // [4H]
                  const float* __restrict__ bhh,   // [4H]
                  const float* __restrict__ Wlin,  // [1, S*H]
                  const float* __restrict__ blin,  // [1]
                  float* __restrict__ out)         // [B,1]
{
    extern __shared__ float sm[];
    float* w_sh = sm;                              // [512][WSTRIDE]
    float* hx   = sm + W_SH_FLOATS;                // [RR][160]
    float* gbuf = hx + HX_FLOATS;                  // [RR][512]

    const int tid = threadIdx.x;
    const int ga  = tid;                           // first gate row
    const int gb  = tid + 256;                     // second gate row
    const int b0  = blockIdx.x * RR;

    // ---- Prologue ----
    unsigned long long wA[36], wB[36];             // Whh[g][0:72) as packed fp32 pairs
    {
        const ulonglong2* pa = reinterpret_cast<const ulonglong2*>(Whh + (size_t)ga * HH);
        const ulonglong2* pb = reinterpret_cast<const ulonglong2*>(Whh + (size_t)gb * HH);
        #pragma unroll
        for (int i = 0; i < 18; i++) {
            ulonglong2 v = pa[i]; wA[2 * i] = v.x; wA[2 * i + 1] = v.y;
            ulonglong2 w = pb[i]; wB[2 * i] = w.x; wB[2 * i + 1] = w.y;
        }
    }
    const float biasA = bih[ga] + bhh[ga];
    const float biasB = bih[gb] + bhh[gb];

    for (int idx = tid; idx < GG * WSM; idx += NTHR) {
        int gg = idx / WSM, i = idx % WSM;
        float v = (i < 56) ? Whh[(size_t)gg * HH + WREG + i]
                           : Wih[(size_t)gg * INW + (i - 56)];
        w_sh[gg * WSTRIDE + i] = v;
    }
    // Zero hx FIRST, barrier, THEN write x(t=0). (R3 bug: these raced on the
    // x-section of hx because the zero loop covers all 640 floats.)
    for (int idx = tid; idx < HX_FLOATS; idx += NTHR) hx[idx] = 0.0f;
    __syncthreads();
    if (tid < RR * INW) {
        int rr = tid >> 5, ii = tid & 31;
        hx[rr * KK + HH + ii] = x[(size_t)(b0 + rr) * SS * INW + ii];   // t = 0
    }

    const int j  = tid & (HH - 1);
    const int r0 = tid >> 7;                       // 0 or 1
    float c0 = 0.0f, c1 = 0.0f;
    float lin0 = 0.0f, lin1 = 0.0f;

    __syncthreads();

    const ulonglong2* wpa = reinterpret_cast<const ulonglong2*>(w_sh + ga * WSTRIDE);
    const ulonglong2* wpb = reinterpret_cast<const ulonglong2*>(w_sh + gb * WSTRIDE);

    // ---- Main sequential loop over timesteps ----
    #pragma unroll 1
    for (int t = 0; t < SS; t++) {
        // Early global loads (latency hidden under the gate GEMM)
        float wl = __ldg(Wlin + (size_t)t * HH + j);
        float xr = 0.0f;
        if (tid < RR * INW) {
            int rr = tid >> 5, ii = tid & 31;
            int tn = (t + 1 < SS) ? (t + 1) : t;
            xr = x[(size_t)(b0 + rr) * SS * INW + (size_t)tn * INW + ii];
        }

        // === Gate phase: 2 gates x 4 rows, software-pipelined quad stream ===
        unsigned long long aA[RR], aB[RR];
        #pragma unroll
        for (int r = 0; r < RR; r++) { aA[r] = 0ull; aB[r] = 0ull; }

        // current operand quads (one per row)
        ulonglong2 hq[RR], hn[RR];
        #pragma unroll
        for (int r = 0; r < RR; r++)
            hq[r] = *reinterpret_cast<const ulonglong2*>(hx + r * KK);

        // Loop A: register-resident weights, quads 0..17
        #pragma unroll
        for (int q = 0; q < 18; q++) {
            #pragma unroll
            for (int r = 0; r < RR; r++)
                hn[r] = *reinterpret_cast<const ulonglong2*>(hx + r * KK + 4 * (q + 1));
            #pragma unroll
            for (int r = 0; r < RR; r++) {
                aA[r] = ffma2(wA[2 * q],     hq[r].x, aA[r]);
                aA[r] = ffma2(wA[2 * q + 1], hq[r].y, aA[r]);
                aB[r] = ffma2(wB[2 * q],     hq[r].x, aB[r]);
                aB[r] = ffma2(wB[2 * q + 1], hq[r].y, aB[r]);
            }
            #pragma unroll
            for (int r = 0; r < RR; r++) hq[r] = hn[r];
        }

        // Loop B: smem weights, quads 18..39 (hx offsets 72..156)
        ulonglong2 wqa = wpa[0], wqb = wpb[0];
        #pragma unroll
        for (int q = 0; q < 22; q++) {
            ulonglong2 wna, wnb;
            if (q < 21) {
                wna = wpa[q + 1];
                wnb = wpb[q + 1];
                #pragma unroll
                for (int r = 0; r < RR; r++)
                    hn[r] = *reinterpret_cast<const ulonglong2*>(hx + r * KK + WREG + 4 * (q + 1));
            }
            #pragma unroll
            for (int r = 0; r < RR; r++) {
                aA[r] = ffma2(wqa.x, hq[r].x, aA[r]);
                aA[r] = ffma2(wqa.y, hq[r].y, aA[r]);
                aB[r] = ffma2(wqb.x, hq[r].x, aB[r]);
                aB[r] = ffma2(wqb.y, hq[r].y, aB[r]);
            }
            if (q < 21) {
                wqa = wna; wqb = wnb;
                #pragma unroll
                for (int r = 0; r < RR; r++) hq[r] = hn[r];
            }
        }

        #pragma unroll
        for (int r = 0; r < RR; r++) {
            float lo, hi;
            unpack2(aA[r], lo, hi);
            gbuf[r * GG + ga] = lo + hi + biasA;
            unpack2(aB[r], lo, hi);
            gbuf[r * GG + gb] = lo + hi + biasB;
        }
        __syncthreads();

        // === Elementwise phase: 2 hidden units per thread ===
        // batch all 8 gate loads first
        const int r1 = r0 + 2;
        float p0i = gbuf[r0 * GG + j];
        float p0f = gbuf[r0 * GG + HH + j];
        float p0g = gbuf[r0 * GG + 2 * HH + j];
        float p0o = gbuf[r0 * GG + 3 * HH + j];
        float p1i = gbuf[r1 * GG + j];
        float p1f = gbuf[r1 * GG + HH + j];
        float p1g = gbuf[r1 * GG + 2 * HH + j];
        float p1o = gbuf[r1 * GG + 3 * HH + j];

        float iv0 = sigmoid_f(p0i), iv1 = sigmoid_f(p1i);
        float fv0 = sigmoid_f(p0f), fv1 = sigmoid_f(p1f);
        float gv0 = tanh_f(p0g),    gv1 = tanh_f(p1g);
        float ov0 = sigmoid_f(p0o), ov1 = sigmoid_f(p1o);
        c0 = fmaf(fv0, c0, iv0 * gv0);
        c1 = fmaf(fv1, c1, iv1 * gv1);
        float hv0 = ov0 * tanh_f(c0);
        float hv1 = ov1 * tanh_f(c1);
        hx[r0 * KK + j] = hv0;
        hx[r1 * KK + j] = hv1;
        lin0 = fmaf(hv0, wl, lin0);
        lin1 = fmaf(hv1, wl, lin1);

        // publish prefetched x for t+1
        if (tid < RR * INW) {
            int rr = tid >> 5, ii = tid & 31;
            hx[rr * KK + HH + ii] = xr;
        }
        __syncthreads();
    }

    // ---- Epilogue: reduce fused-linear accumulators ----
    float v0 = lin0, v1 = lin1;
    #pragma unroll
    for (int off = 16; off; off >>= 1) {
        v0 += __shfl_xor_sync(0xffffffffu, v0, off);
        v1 += __shfl_xor_sync(0xffffffffu, v1, off);
    }
    const int wi = tid >> 5;                       // warp id 0..7
    if ((tid & 31) == 0) {
        gbuf[(wi >> 2) * 4 + (wi & 3)]       = v0;   // rows 0/1
        gbuf[(2 + (wi >> 2)) * 4 + (wi & 3)] = v1;   // rows 2/3
    }
    __syncthreads();
    if (tid < RR) {
        float s = gbuf[4 * tid] + gbuf[4 * tid + 1] + gbuf[4 * tid + 2] + gbuf[4 * tid + 3];
        out[b0 + tid] = s + blin[0];
    }
}

extern "C" void kernel_launch(void* const* d_in, const int* in_sizes, int n_in,
                              void* d_out, int out_size)
{
    const float* x    = (const float*)d_in[0];
    const float* Wih  = (const float*)d_in[1];
    const float* Whh  = (const float*)d_in[2];
    const float* bih  = (const float*)d_in[3];
    const float* bhh  = (const float*)d_in[4];
    const float* Wlin = (const float*)d_in[5];
    const float* blin = (const float*)d_in[6];
    float* out = (float*)d_out;

    cudaFuncSetAttribute(lstm_fused_kernel,
                         cudaFuncAttributeMaxDynamicSharedMemorySize, SMEM_BYTES);
    lstm_fused_kernel<<<NBLK, NTHR, SMEM_BYTES>>>(x, Wih, Whh, bih, bhh, Wlin, blin, out);
}